// round 10
// baseline (speedup 1.0000x reference)
#include <cuda_runtime.h>
#include <cstdint>

// Problem constants
#define Bsz   4096
#define CL    8192      // C*L = 8*1024 (GEMM K dim)
#define Hdim  1024
#define Kdim  64
#define Tsteps 32
#define BETA_F 0.9f

// Device scratch (allocation-free rule: use __device__ globals)
__device__ float    g_I1[(size_t)Bsz * Hdim];     // 16 MB
__device__ uint32_t g_P [(size_t)Bsz * Hdim];     // 16 MB spike bit-patterns
__device__ float    g_W2T[(size_t)Hdim * Kdim];   // 256 KB  W2 transposed [h][k]

// ---------------------------------------------------------------------------
// Kernel A: fp32 NT GEMM   I1[b][h] = sum_k x[b][k] * W1[h][k]
// BM=128, BN=64, BK=16, TM=8, TN=4, 256 threads.
//
// NUMERICS HYPOTHESIS (this round's probe): reference reduction =
//   4 contiguous chunks of 2048, each chunk a SINGLE-accumulator strictly
//   ascending-k FMA chain, chunks combined by ascending adds.
// This is simultaneously (a) Eigen gebp with kc=2048 (Grace 64KB L1d,
// kdiv=32) with C += per-panel, and (b) cublas splitK=4 contiguous partials
// (outer combine order differs by <= 1 ulp of the total, ~1e-7 -> no flips).
// Fit evidence: observed flip ratio serial/exact = 1.743 == predicted
// diff(serial, chunk2048)/delta(chunk2048) = sqrt(16-4)/2.
// ---------------------------------------------------------------------------
__global__ void __launch_bounds__(256) sgemm_nt_chunk2048_kernel(
    const float* __restrict__ A,   // [4096][8192]
    const float* __restrict__ Bw)  // [1024][8192]
{
    __shared__ __align__(16) float As[16][132];  // [k][m]
    __shared__ __align__(16) float Bs[16][68];   // [k][n]

    const int tid = threadIdx.x;
    const int tx  = tid & 15;      // n-dir: 16 threads * TN=4 -> 64
    const int ty  = tid >> 4;      // m-dir: 16 threads * TM=8 -> 128
    const int ra  = tid >> 2;      // 0..63 load row
    const int ka  = (tid & 3) << 2;// 0,4,8,12 load k-offset

    const float* Ap = A  + ((size_t)blockIdx.y * 128 + ra) * CL + ka;
    const float* Bp = Bw + ((size_t)blockIdx.x * 64  + ra) * CL + ka;

    float4 a0 = *(const float4*)(Ap);
    float4 a1 = *(const float4*)(Ap + (size_t)64 * CL);
    float4 b0 = *(const float4*)(Bp);

    float acc[8][4];    // inner chunk accumulator (ascending FMA, 2048 terms)
    float accT[8][4];   // outer running sum (ascending adds across chunks)
    #pragma unroll
    for (int i = 0; i < 8; ++i)
        #pragma unroll
        for (int j = 0; j < 4; ++j) { acc[i][j] = 0.f; accT[i][j] = 0.f; }

    int tile = 0;
    for (int k0 = 0; k0 < CL; k0 += 16, ++tile) {
        As[ka+0][ra]    = a0.x; As[ka+1][ra]    = a0.y;
        As[ka+2][ra]    = a0.z; As[ka+3][ra]    = a0.w;
        As[ka+0][ra+64] = a1.x; As[ka+1][ra+64] = a1.y;
        As[ka+2][ra+64] = a1.z; As[ka+3][ra+64] = a1.w;
        Bs[ka+0][ra]    = b0.x; Bs[ka+1][ra]    = b0.y;
        Bs[ka+2][ra]    = b0.z; Bs[ka+3][ra]    = b0.w;
        __syncthreads();

        if (k0 + 16 < CL) {                 // prefetch next tile
            a0 = *(const float4*)(Ap + k0 + 16);
            a1 = *(const float4*)(Ap + (size_t)64 * CL + k0 + 16);
            b0 = *(const float4*)(Bp + k0 + 16);
        }

        #pragma unroll
        for (int kk = 0; kk < 16; ++kk) {   // strictly ascending k
            float4 av0 = *(const float4*)(&As[kk][ty * 8]);
            float4 av1 = *(const float4*)(&As[kk][ty * 8 + 4]);
            float4 bv  = *(const float4*)(&Bs[kk][tx * 4]);
            float ar[8] = {av0.x, av0.y, av0.z, av0.w,
                           av1.x, av1.y, av1.z, av1.w};
            float br[4] = {bv.x, bv.y, bv.z, bv.w};
            #pragma unroll
            for (int i = 0; i < 8; ++i)
                #pragma unroll
                for (int j = 0; j < 4; ++j)
                    acc[i][j] = fmaf(ar[i], br[j], acc[i][j]);
        }

        // flush inner chunk every 128 tiles (= 2048 k-terms), ascending adds
        if ((tile & 127) == 127) {
            #pragma unroll
            for (int i = 0; i < 8; ++i)
                #pragma unroll
                for (int j = 0; j < 4; ++j) {
                    accT[i][j] = __fadd_rn(accT[i][j], acc[i][j]);
                    acc[i][j] = 0.f;
                }
        }
        __syncthreads();
    }

    float* Cp = g_I1 + ((size_t)blockIdx.y * 128 + ty * 8) * Hdim
                     + blockIdx.x * 64 + tx * 4;
    #pragma unroll
    for (int i = 0; i < 8; ++i) {
        float4 v = make_float4(accT[i][0], accT[i][1], accT[i][2], accT[i][3]);
        *(float4*)(Cp + (size_t)i * Hdim) = v;
    }
}

// ---------------------------------------------------------------------------
// Kernel B: per-(b,h) LIF layer-1 recurrence -> 32-bit spike pattern.
// Non-contracted mul+add (proven flip-neutral vs FMA; matches XLA default).
// ---------------------------------------------------------------------------
__global__ void spike_kernel()
{
    const size_t i = (size_t)blockIdx.x * blockDim.x + threadIdx.x;
    const float I = g_I1[i];
    float v = 0.f;
    uint32_t p = 0u;
    #pragma unroll
    for (int t = 0; t < Tsteps; ++t) {
        v = __fadd_rn(__fmul_rn(BETA_F, v), I);
        if (__fsub_rn(v, 1.0f) >= 0.0f) { p |= (1u << t); v = __fsub_rn(v, 1.0f); }
    }
    g_P[i] = p;
}

// ---------------------------------------------------------------------------
// Kernel T: transpose W2[k][h] -> g_W2T[h][k] (coalesced layer-2 reads)
// ---------------------------------------------------------------------------
__global__ void w2t_kernel(const float* __restrict__ W2)
{
    const int i = blockIdx.x * blockDim.x + threadIdx.x; // over Kdim*Hdim
    const int k = i >> 10;       // /Hdim
    const int h = i & 1023;      // %Hdim
    g_W2T[h * Kdim + k] = W2[i];
}

// ---------------------------------------------------------------------------
// Kernel C: layer-2.  Block = 4 batch rows x 64 k (256 threads).
// c[t]: chunk-32 inner + Kahan outer (delta ~6e-8; R3==R7 proved layer-2
// accumulation noise is flip-free at this level). Silent-neuron skip is an
// exact no-op vs the reference's adds of rn(0*w)=0.
// v2 recurrence: non-contracted mul+add.
// ---------------------------------------------------------------------------
__global__ void __launch_bounds__(256) layer2_kernel(float* __restrict__ out)
{
    __shared__ uint32_t sP[4][Hdim];

    const int bl = threadIdx.x >> 6;   // local batch 0..3
    const int k  = threadIdx.x & 63;
    const int b0 = blockIdx.x * 4;

    for (int i = threadIdx.x; i < 4 * Hdim; i += 256)
        sP[i >> 10][i & 1023] = g_P[(size_t)(b0 + (i >> 10)) * Hdim + (i & 1023)];
    __syncthreads();

    float c[Tsteps], comp[Tsteps];
    #pragma unroll
    for (int t = 0; t < Tsteps; ++t) { c[t] = 0.f; comp[t] = 0.f; }

    for (int hb = 0; hb < Hdim; hb += 32) {
        float inner[Tsteps];
        #pragma unroll
        for (int t = 0; t < Tsteps; ++t) inner[t] = 0.f;

        #pragma unroll 4
        for (int h = hb; h < hb + 32; ++h) {
            const uint32_t p = sP[bl][h];   // warp-uniform
            if (p) {
                const float w = g_W2T[h * Kdim + k];
                #pragma unroll
                for (int t = 0; t < Tsteps; ++t)
                    if (p & (1u << t)) inner[t] = __fadd_rn(inner[t], w);
            }
        }

        #pragma unroll
        for (int t = 0; t < Tsteps; ++t) {
            float y = __fsub_rn(inner[t], comp[t]);
            float s = __fadd_rn(c[t], y);
            float u = __fsub_rn(s, c[t]);
            comp[t] = __fsub_rn(u, y);
            c[t] = s;
        }
    }

    float v2 = 0.f, cnt = 0.f;
    #pragma unroll
    for (int t = 0; t < Tsteps; ++t) {
        const float ct = __fsub_rn(c[t], comp[t]);
        v2 = __fadd_rn(__fmul_rn(BETA_F, v2), ct);
        if (__fsub_rn(v2, 1.0f) >= 0.0f) { v2 = __fsub_rn(v2, 1.0f); cnt += 1.0f; }
    }
    out[(size_t)(b0 + bl) * Kdim + k] = cnt;
}

// ---------------------------------------------------------------------------
extern "C" void kernel_launch(void* const* d_in, const int* in_sizes, int n_in,
                              void* d_out, int out_size)
{
    const float* x  = (const float*)d_in[0];   // (4096, 8, 1024) == (4096, 8192)
    const float* W1 = (const float*)d_in[1];   // (1024, 8192)
    const float* W2 = (const float*)d_in[2];   // (64, 1024)
    float* out = (float*)d_out;                // (4096, 64)

    // W2 transpose (independent of GEMM, tiny)
    w2t_kernel<<<(Kdim * Hdim) / 256, 256>>>(W2);

    // I1 = x @ W1^T  (chunk-2048 ascending FMA, ascending outer adds)
    dim3 grid(Hdim / 64, Bsz / 128);
    sgemm_nt_chunk2048_kernel<<<grid, 256>>>(x, W1);

    // spike trains
    spike_kernel<<<(Bsz * Hdim) / 256, 256>>>();

    // layer 2 + counts
    layer2_kernel<<<Bsz / 4, 256>>>(out);
}